// round 12
// baseline (speedup 1.0000x reference)
#include <cuda_runtime.h>
#include <math.h>

#define N    2708
#define INC  1433
#define OC   128
#define NCH  32
#define RC   85      // ceil(N/NCH)
#define GZ   4       // gemm K-split
#define ARPB 20      // attn rows per block -> 136 blocks
#define ATHR 128
#define AJT  32      // attn j-tile
#define NWRD 85      // ceil(N/32) bitmask words per row
#define NWRDP 88     // NWRD padded to multiple of 4 (uniform warp trip count)
#define NW4  677     // N/4

#define GEMM_BLKS 680          // 2 x 85 x 4
#define CP_JBLK   22           // ceil(N/128) colpart j-blocks
#define CP_BLKS   (CP_JBLK * NCH)   // 704
#define FOLD_BLKS 339          // ceil(N*OC/4 / 256)
#define CR_BLKS   11           // ceil(N/256)

// ---------------- scratch (static device memory) -----------------------------
__device__ __align__(16) float g_Kp[GZ][N * OC];
__device__ __align__(16) float g_K[N * OC];
__device__ float g_w1[INC], g_w2[INC];
__device__ float g_k1[N], g_k2[N];
__device__ float g_part1[NCH * N], g_part2[NCH * N];
__device__ float g_s1[N], g_s2[N];
__device__ float g_p[N], g_q[N];

__device__ __forceinline__ unsigned su32(const void* p) {
    return (unsigned)__cvta_generic_to_shared(p);
}
#define CP16(dst, src) asm volatile("cp.async.cg.shared.global [%0], [%1], 16;" :: "r"(dst), "l"(src) : "memory")
#define CPCOMMIT()     asm volatile("cp.async.commit_group;" ::: "memory")
#define CPWAIT0()      asm volatile("cp.async.wait_group 0;" ::: "memory")

// ---------------- w1 = W^T a1, w2 = W^T a2 ------------------------------------
__global__ void wcalc(const float* __restrict__ W, const float* __restrict__ a1,
                      const float* __restrict__ a2) {
    __shared__ float a1s[OC], a2s[OC];
    int t = threadIdx.x;
    if (t < OC) { a1s[t] = a1[t]; a2s[t] = a2[t]; }
    __syncthreads();
    int c = blockIdx.x * 128 + t;
    if (c >= INC) return;
    float w1 = 0.f, w2 = 0.f;
#pragma unroll 4
    for (int o = 0; o < OC; o++) {
        float wv = W[(size_t)o * INC + c];
        w1 += wv * a1s[o];
        w2 += wv * a2s[o];
    }
    g_w1[c] = w1;
    g_w2[c] = w2;
}

// ---------------- k1 = X w1, k2 = X w2 (one warp per row) ---------------------
__global__ void k1k2x(const float* __restrict__ X) {
    __shared__ float w1s[INC], w2s[INC];
    int t = threadIdx.x;
    for (int c = t; c < INC; c += 256) { w1s[c] = g_w1[c]; w2s[c] = g_w2[c]; }
    __syncthreads();
    int wp = t >> 5, lane = t & 31;
    int i = blockIdx.x * 8 + wp;
    if (i >= N) return;
    const float* Xr = X + (size_t)i * INC;
    float d1 = 0.f, d2 = 0.f;
    for (int c = lane; c < INC; c += 32) {
        float xv = Xr[c];
        d1 += xv * w1s[c];
        d2 += xv * w2s[c];
    }
#pragma unroll
    for (int off = 16; off; off >>= 1) {
        d1 += __shfl_down_sync(0xffffffffu, d1, off);
        d2 += __shfl_down_sync(0xffffffffu, d2, off);
    }
    if (lane == 0) { g_k1[i] = d1; g_k2[i] = d2; }
}

// ---------------- combo: gemm (K = X W^T partials) || colpart -----------------
// Blocks [0, GEMM_BLKS): gemm, 128 thr, BM=32 BN=64 BK=16, 4x4 reg tile.
// Blocks [GEMM_BLKS, GEMM_BLKS+CP_BLKS): colpart (t1 = U^T k1, t2 = U^T 1).
__global__ void __launch_bounds__(128) combo_gp(const float* __restrict__ X,
                                                const float* __restrict__ W,
                                                const float* __restrict__ U) {
    int b = blockIdx.x;
    int t = threadIdx.x;
    if (b < GEMM_BLKS) {
        __shared__ __align__(16) float Xs[16][36];
        __shared__ __align__(16) float Ws[16][68];
        int z   = b / 170;
        int rem = b % 170;
        int c0  = (rem & 1) * 64;
        int i0  = (rem >> 1) * 32;
        int kb = (INC * z) / GZ;
        int ke = (INC * (z + 1)) / GZ;
        int tx = t & 15;
        int ty = t >> 4;
        float acc[4][4] = {};
        float xr[4], wr[8];

#pragma unroll
        for (int l = 0; l < 4; l++) {
            int e = t + l * 128;
            int r = e >> 4, kk = e & 15;
            int gi = i0 + r, gk = kb + kk;
            xr[l] = (gi < N && gk < ke) ? X[(size_t)gi * INC + gk] : 0.f;
        }
#pragma unroll
        for (int l = 0; l < 8; l++) {
            int e = t + l * 128;
            int c = e >> 4, kk = e & 15;
            int gk = kb + kk;
            wr[l] = (gk < ke) ? W[(size_t)(c0 + c) * INC + gk] : 0.f;
        }

        for (int kt = kb; kt < ke; kt += 16) {
#pragma unroll
            for (int l = 0; l < 4; l++) { int e = t + l * 128; Xs[e & 15][e >> 4] = xr[l]; }
#pragma unroll
            for (int l = 0; l < 8; l++) { int e = t + l * 128; Ws[e & 15][e >> 4] = wr[l]; }
            __syncthreads();
            int ktn = kt + 16;
            if (ktn < ke) {
#pragma unroll
                for (int l = 0; l < 4; l++) {
                    int e = t + l * 128;
                    int r = e >> 4, kk = e & 15;
                    int gi = i0 + r, gk = ktn + kk;
                    xr[l] = (gi < N && gk < ke) ? X[(size_t)gi * INC + gk] : 0.f;
                }
#pragma unroll
                for (int l = 0; l < 8; l++) {
                    int e = t + l * 128;
                    int c = e >> 4, kk = e & 15;
                    int gk = ktn + kk;
                    wr[l] = (gk < ke) ? W[(size_t)(c0 + c) * INC + gk] : 0.f;
                }
            }
#pragma unroll
            for (int kk = 0; kk < 16; kk++) {
                float4 a = *(const float4*)&Xs[kk][4 * ty];
                float4 bb = *(const float4*)&Ws[kk][4 * tx];
                acc[0][0] += a.x * bb.x; acc[0][1] += a.x * bb.y; acc[0][2] += a.x * bb.z; acc[0][3] += a.x * bb.w;
                acc[1][0] += a.y * bb.x; acc[1][1] += a.y * bb.y; acc[1][2] += a.y * bb.z; acc[1][3] += a.y * bb.w;
                acc[2][0] += a.z * bb.x; acc[2][1] += a.z * bb.y; acc[2][2] += a.z * bb.z; acc[2][3] += a.z * bb.w;
                acc[3][0] += a.w * bb.x; acc[3][1] += a.w * bb.y; acc[3][2] += a.w * bb.z; acc[3][3] += a.w * bb.w;
            }
            __syncthreads();
        }
#pragma unroll
        for (int rr = 0; rr < 4; rr++) {
            int gi = i0 + 4 * ty + rr;
            if (gi < N) {
                float4 v = make_float4(acc[rr][0], acc[rr][1], acc[rr][2], acc[rr][3]);
                *(float4*)&g_Kp[z][(size_t)gi * OC + c0 + 4 * tx] = v;
            }
        }
    } else {
        // colpart: t1 = U^T k1, t2 = U^T 1 over row-chunk ch
        int bb = b - GEMM_BLKS;
        int ch = bb / CP_JBLK;
        int j  = (bb % CP_JBLK) * 128 + t;
        if (j >= N) return;
        int ib = ch * RC;
        int ie = min(N, ib + RC);
        float a = 0.f, s = 0.f;
#pragma unroll 4
        for (int i = ib; i < ie; i++) {
            float u = U[(size_t)i * N + j];
            a += u * g_k1[i];
            s += u;
        }
        g_part1[ch * N + j] = a;
        g_part2[ch * N + j] = s;
    }
}

// ---------------- combo: fold (g_K = sum_z g_Kp) || colreduce ------------------
__global__ void combo_fc(const float* __restrict__ lmbd) {
    int b = blockIdx.x;
    int t = threadIdx.x;
    if (b < FOLD_BLKS) {
        int i = b * 256 + t;
        if (i >= (N * OC) / 4) return;
        const float4* p0 = (const float4*)g_Kp[0];
        const float4* p1 = (const float4*)g_Kp[1];
        const float4* p2 = (const float4*)g_Kp[2];
        const float4* p3 = (const float4*)g_Kp[3];
        float4 a = p0[i], bb = p1[i], c = p2[i], d = p3[i];
        float4 v = make_float4(a.x + bb.x + c.x + d.x, a.y + bb.y + c.y + d.y,
                               a.z + bb.z + c.z + d.z, a.w + bb.w + c.w + d.w);
        ((float4*)g_K)[i] = v;
    } else {
        int j = (b - FOLD_BLKS) * 256 + t;
        if (j >= N) return;
        float a = 0.f, s = 0.f;
#pragma unroll
        for (int c = 0; c < NCH; c++) {
            a += g_part1[c * N + j];
            s += g_part2[c * N + j];
        }
        float l = lmbd[j];
        g_s1[j] = l * a;
        g_s2[j] = l * s;
    }
}

// ---------------- p = U s1, q = U s2 -------------------------------------------
__global__ void pq_kernel(const float* __restrict__ U) {
    __shared__ float r1[256], r2[256];
    int i = blockIdx.x;
    int t = threadIdx.x;
    float a = 0.f, b = 0.f;
    const float4* Ur = (const float4*)(U + (size_t)i * N);
    for (int j4 = t; j4 < NW4; j4 += 256) {
        float4 u = Ur[j4];
        int j = 4 * j4;
        a += u.x * g_s1[j] + u.y * g_s1[j + 1] + u.z * g_s1[j + 2] + u.w * g_s1[j + 3];
        b += u.x * g_s2[j] + u.y * g_s2[j + 1] + u.z * g_s2[j + 2] + u.w * g_s2[j + 3];
    }
    r1[t] = a; r2[t] = b;
    __syncthreads();
    for (int s = 128; s; s >>= 1) {
        if (t < s) { r1[t] += r1[t + s]; r2[t] += r2[t + s]; }
        __syncthreads();
    }
    if (t == 0) { g_p[i] = r1[0]; g_q[i] = r2[0]; }
}

// ---------------- fused masked-softmax + H = alpha @ K -------------------------
__global__ void __launch_bounds__(ATHR) attn_h(const int* __restrict__ A, float* __restrict__ H) {
    __shared__ __align__(16) float4 Ksh[2][AJT][32];   // 32 KB
    __shared__ float    wsh[2][32][AJT];               // 8 KB
    __shared__ unsigned msk[ARPB][NWRD];               // 6.8 KB
    __shared__ float    pm[ARPB], qm[ARPB], mmf[ARPB];

    int i0 = blockIdx.x * ARPB;
    int t  = threadIdx.x;
    int lane = t & 31;
    int wp   = t >> 5;
    const float4* Kf4 = (const float4*)g_K;

#pragma unroll
    for (int l = 0; l < 8; l++) {
        int e = t + l * ATHR;
        int jj = e >> 5, c4 = e & 31;
        CP16(su32(&Ksh[0][jj][c4]), &Kf4[(size_t)jj * 32 + c4]);
    }
    CPCOMMIT();

    if (t < ARPB) {
        int gi = i0 + t;
        bool v = (gi < N);
        pm[t] = v ? g_p[gi] : 0.f;
        qm[t] = v ? g_q[gi] : 0.f;
    }
    __syncthreads();

    // Phase 1: bitmask + masked row max, uniform trip count (no shfl divergence)
    {
        int g8 = lane >> 3, l8 = lane & 7;
#pragma unroll
        for (int rr = 0; rr < 5; rr++) {
            int r  = 5 * wp + rr;
            int gi = i0 + r;
            float mloc = 0.f;
            bool rowok = (gi < N);
            float pr = rowok ? pm[r] : 0.f;
            float qr = rowok ? qm[r] : 0.f;
            const int4* Ap = (const int4*)(A + (size_t)(rowok ? gi : 0) * N);
            for (int b = g8; b < NWRDP; b += 4) {
                int j0 = 32 * b + 4 * l8;
                unsigned nib = 0;
                if (rowok && b < NWRD && j0 < N) {
                    int4 av = Ap[8 * b + l8];
#define PROC(v, jj_, bitn)                                                  \
                    if (v) {                                                \
                        nib |= (1u << (bitn));                              \
                        float x = fabsf(pr + qr * __ldg(&g_k2[jj_]));       \
                        mloc = fmaxf(mloc, x);                              \
                    }
                    PROC(av.x, j0 + 0, 0)
                    PROC(av.y, j0 + 1, 1)
                    PROC(av.z, j0 + 2, 2)
                    PROC(av.w, j0 + 3, 3)
#undef PROC
                }
                unsigned bits = nib << (4 * l8);
                bits |= __shfl_xor_sync(0xffffffffu, bits, 1);
                bits |= __shfl_xor_sync(0xffffffffu, bits, 2);
                bits |= __shfl_xor_sync(0xffffffffu, bits, 4);
                if (l8 == 0 && b < NWRD) msk[r][b] = rowok ? bits : 0u;
            }
#pragma unroll
            for (int off = 16; off; off >>= 1)
                mloc = fmaxf(mloc, __shfl_xor_sync(0xffffffffu, mloc, off));
            if (lane == 0) mmf[r] = mloc;
        }
    }
    __syncthreads();

    float wsum[5] = {0.f, 0.f, 0.f, 0.f, 0.f};
    {
        float k2v = __ldg(&g_k2[lane]);
        unsigned bit = 1u << lane;
#pragma unroll
        for (int rr = 0; rr < 5; rr++) {
            int r = 5 * wp + rr;
            float wv = 0.f;
            if (msk[r][0] & bit)
                wv = __expf(fabsf(pm[r] + qm[r] * k2v) - mmf[r]);
            wsh[0][8 * wp + rr][lane] = wv;
            wsum[rr] += wv;
        }
    }
    CPWAIT0();
    __syncthreads();

    float4 acc[5];
#pragma unroll
    for (int rr = 0; rr < 5; rr++) acc[rr] = make_float4(0.f, 0.f, 0.f, 0.f);

    int buf = 0;
    for (int j0 = 0; j0 < N; j0 += AJT) {
        int jn = j0 + AJT;
        if (jn < N) {
            int nb = buf ^ 1;
#pragma unroll
            for (int l = 0; l < 8; l++) {
                int e = t + l * ATHR;
                int jj = e >> 5, c4 = e & 31;
                int gj = jn + jj;
                if (gj < N) CP16(su32(&Ksh[nb][jj][c4]), &Kf4[(size_t)gj * 32 + c4]);
                else        Ksh[nb][jj][c4] = make_float4(0.f, 0.f, 0.f, 0.f);
            }
            CPCOMMIT();
            int gj = jn + lane;
            bool okj = (gj < N);
            float k2v = okj ? __ldg(&g_k2[gj]) : 0.f;
            int wrd = gj >> 5;
            unsigned bit = 1u << (gj & 31);
#pragma unroll
            for (int rr = 0; rr < 5; rr++) {
                int r = 5 * wp + rr;
                float wv = 0.f;
                if (okj && (msk[r][wrd] & bit))
                    wv = __expf(fabsf(pm[r] + qm[r] * k2v) - mmf[r]);
                wsh[nb][8 * wp + rr][lane] = wv;
                wsum[rr] += wv;
            }
        }
#pragma unroll 4
        for (int jj = 0; jj < AJT; jj++) {
            float4 kv = Ksh[buf][jj][lane];
            float w0 = wsh[buf][8 * wp + 0][jj];
            float w1 = wsh[buf][8 * wp + 1][jj];
            float w2 = wsh[buf][8 * wp + 2][jj];
            float w3 = wsh[buf][8 * wp + 3][jj];
            float w4 = wsh[buf][8 * wp + 4][jj];
            acc[0].x += w0 * kv.x; acc[0].y += w0 * kv.y; acc[0].z += w0 * kv.z; acc[0].w += w0 * kv.w;
            acc[1].x += w1 * kv.x; acc[1].y += w1 * kv.y; acc[1].z += w1 * kv.z; acc[1].w += w1 * kv.w;
            acc[2].x += w2 * kv.x; acc[2].y += w2 * kv.y; acc[2].z += w2 * kv.z; acc[2].w += w2 * kv.w;
            acc[3].x += w3 * kv.x; acc[3].y += w3 * kv.y; acc[3].z += w3 * kv.z; acc[3].w += w3 * kv.w;
            acc[4].x += w4 * kv.x; acc[4].y += w4 * kv.y; acc[4].z += w4 * kv.z; acc[4].w += w4 * kv.w;
        }
        if (jn < N) CPWAIT0();
        __syncthreads();
        buf ^= 1;
    }

#pragma unroll
    for (int rr = 0; rr < 5; rr++) {
#pragma unroll
        for (int off = 16; off; off >>= 1)
            wsum[rr] += __shfl_xor_sync(0xffffffffu, wsum[rr], off);
        int gi = i0 + 5 * wp + rr;
        if (gi < N) {
            float s = (wsum[rr] > 0.f) ? 1.f / wsum[rr] : 0.f;
            float4 v = acc[rr];
            v.x *= s; v.y *= s; v.z *= s; v.w *= s;
            ((float4*)H)[(size_t)gi * 32 + lane] = v;
        }
    }
}

// ---------------- launch --------------------------------------------------------
extern "C" void kernel_launch(void* const* d_in, const int* in_sizes, int n_in,
                              void* d_out, int out_size) {
    (void)in_sizes; (void)n_in; (void)out_size;
    const float* X    = (const float*)d_in[0];
    const int*   A    = (const int*)d_in[1];
    const float* U    = (const float*)d_in[2];
    const float* W    = (const float*)d_in[3];
    const float* a1   = (const float*)d_in[4];
    const float* a2   = (const float*)d_in[5];
    const float* lmbd = (const float*)d_in[6];
    float* H = (float*)d_out;

    wcalc    <<<(INC + 127) / 128, 128>>>(W, a1, a2);
    k1k2x    <<<(N + 7) / 8, 256>>>(X);
    combo_gp <<<GEMM_BLKS + CP_BLKS, 128>>>(X, W, U);
    combo_fc <<<FOLD_BLKS + CR_BLKS, 256>>>(lmbd);
    pq_kernel<<<N, 256>>>(U);
    attn_h   <<<(N + ARPB - 1) / ARPB, ATHR>>>(A, H);
}

// round 13
// speedup vs baseline: 2.0907x; 2.0907x over previous
#include <cuda_runtime.h>
#include <math.h>

#define N    2708
#define INC  1433
#define OC   128
#define NCH  32
#define RC   85      // ceil(N/NCH)
#define GZ   4       // gemm K-split
#define NW4  677     // N/4
#define NPAD 2816    // 22*128, uniform compaction trip count
#define XTHR 25.0f   // exp cutoff: dropped mass < N*exp(-25) ~ 4e-8

// ---------------- scratch (static device memory) -----------------------------
__device__ __align__(16) float g_Kp[GZ][N * OC];
__device__ __align__(16) float g_K[N * OC];
__device__ float g_k1[N], g_k2[N];
__device__ float g_part1[NCH * N], g_part2[NCH * N];
__device__ float g_s1[N], g_s2[N];
__device__ float g_p[N], g_q[N];

// ---------------- K = X @ W^T, K-split, register-pipelined --------------------
__global__ void gemm_k(const float* __restrict__ X, const float* __restrict__ W) {
    __shared__ __align__(16) float Xs[16][36];
    __shared__ __align__(16) float Ws[16][68];
    int i0 = blockIdx.y * 32;
    int c0 = blockIdx.x * 64;
    int z  = blockIdx.z;
    int kb = (INC * z) / GZ;
    int ke = (INC * (z + 1)) / GZ;
    int t  = threadIdx.x;
    int tx = t & 15;
    int ty = t >> 4;
    float acc[4][4] = {};
    float xr[4], wr[8];

#pragma unroll
    for (int l = 0; l < 4; l++) {
        int e = t + l * 128;
        int r = e >> 4, kk = e & 15;
        int gi = i0 + r, gk = kb + kk;
        xr[l] = (gi < N && gk < ke) ? X[(size_t)gi * INC + gk] : 0.f;
    }
#pragma unroll
    for (int l = 0; l < 8; l++) {
        int e = t + l * 128;
        int c = e >> 4, kk = e & 15;
        int gk = kb + kk;
        wr[l] = (gk < ke) ? W[(size_t)(c0 + c) * INC + gk] : 0.f;
    }

    for (int kt = kb; kt < ke; kt += 16) {
#pragma unroll
        for (int l = 0; l < 4; l++) { int e = t + l * 128; Xs[e & 15][e >> 4] = xr[l]; }
#pragma unroll
        for (int l = 0; l < 8; l++) { int e = t + l * 128; Ws[e & 15][e >> 4] = wr[l]; }
        __syncthreads();
        int ktn = kt + 16;
        if (ktn < ke) {
#pragma unroll
            for (int l = 0; l < 4; l++) {
                int e = t + l * 128;
                int r = e >> 4, kk = e & 15;
                int gi = i0 + r, gk = ktn + kk;
                xr[l] = (gi < N && gk < ke) ? X[(size_t)gi * INC + gk] : 0.f;
            }
#pragma unroll
            for (int l = 0; l < 8; l++) {
                int e = t + l * 128;
                int c = e >> 4, kk = e & 15;
                int gk = ktn + kk;
                wr[l] = (gk < ke) ? W[(size_t)(c0 + c) * INC + gk] : 0.f;
            }
        }
#pragma unroll
        for (int kk = 0; kk < 16; kk++) {
            float4 a = *(const float4*)&Xs[kk][4 * ty];
            float4 b = *(const float4*)&Ws[kk][4 * tx];
            acc[0][0] += a.x * b.x; acc[0][1] += a.x * b.y; acc[0][2] += a.x * b.z; acc[0][3] += a.x * b.w;
            acc[1][0] += a.y * b.x; acc[1][1] += a.y * b.y; acc[1][2] += a.y * b.z; acc[1][3] += a.y * b.w;
            acc[2][0] += a.z * b.x; acc[2][1] += a.z * b.y; acc[2][2] += a.z * b.z; acc[2][3] += a.z * b.w;
            acc[3][0] += a.w * b.x; acc[3][1] += a.w * b.y; acc[3][2] += a.w * b.z; acc[3][3] += a.w * b.w;
        }
        __syncthreads();
    }
#pragma unroll
    for (int rr = 0; rr < 4; rr++) {
        int gi = i0 + 4 * ty + rr;
        if (gi < N) {
            float4 v = make_float4(acc[rr][0], acc[rr][1], acc[rr][2], acc[rr][3]);
            *(float4*)&g_Kp[z][(size_t)gi * OC + c0 + 4 * tx] = v;
        }
    }
}

// ---------------- fold GZ partials -> g_K, plus k1,k2 (one warp/row) ---------
__global__ void fold_k1k2(const float* __restrict__ a1, const float* __restrict__ a2) {
    int w = threadIdx.x >> 5;
    int lane = threadIdx.x & 31;
    int i = blockIdx.x * 8 + w;
    if (i >= N) return;
    float d1 = 0.f, d2 = 0.f;
#pragma unroll
    for (int u = 0; u < 4; u++) {
        int c = lane + 32 * u;
        size_t idx = (size_t)i * OC + c;
        float kv = g_Kp[0][idx] + g_Kp[1][idx] + g_Kp[2][idx] + g_Kp[3][idx];
        g_K[idx] = kv;
        d1 += kv * a1[c];
        d2 += kv * a2[c];
    }
#pragma unroll
    for (int off = 16; off; off >>= 1) {
        d1 += __shfl_down_sync(0xffffffffu, d1, off);
        d2 += __shfl_down_sync(0xffffffffu, d2, off);
    }
    if (lane == 0) { g_k1[i] = d1; g_k2[i] = d2; }
}

// ---------------- column partials: t1 = U^T k1, t2 = U^T 1 --------------------
__global__ void colpart(const float* __restrict__ U) {
    int j  = blockIdx.x * 256 + threadIdx.x;
    int ch = blockIdx.y;
    if (j >= N) return;
    int ib = ch * RC;
    int ie = min(N, ib + RC);
    float a = 0.f, b = 0.f;
    for (int i = ib; i < ie; i++) {
        float u = U[(size_t)i * N + j];
        a += u * g_k1[i];
        b += u;
    }
    g_part1[ch * N + j] = a;
    g_part2[ch * N + j] = b;
}

// ---------------- s = lmbd * t -------------------------------------------------
__global__ void colreduce(const float* __restrict__ lmbd) {
    int j = blockIdx.x * 256 + threadIdx.x;
    if (j >= N) return;
    float a = 0.f, b = 0.f;
#pragma unroll
    for (int c = 0; c < NCH; c++) {
        a += g_part1[c * N + j];
        b += g_part2[c * N + j];
    }
    float l = lmbd[j];
    g_s1[j] = l * a;
    g_s2[j] = l * b;
}

// ---------------- p = U s1, q = U s2 -------------------------------------------
__global__ void pq_kernel(const float* __restrict__ U) {
    __shared__ float r1[256], r2[256];
    int i = blockIdx.x;
    int t = threadIdx.x;
    float a = 0.f, b = 0.f;
    const float4* Ur = (const float4*)(U + (size_t)i * N);
    for (int j4 = t; j4 < NW4; j4 += 256) {
        float4 u = Ur[j4];
        int j = 4 * j4;
        a += u.x * g_s1[j] + u.y * g_s1[j + 1] + u.z * g_s1[j + 2] + u.w * g_s1[j + 3];
        b += u.x * g_s2[j] + u.y * g_s2[j + 1] + u.z * g_s2[j + 2] + u.w * g_s2[j + 3];
    }
    r1[t] = a; r2[t] = b;
    __syncthreads();
    for (int s = 128; s; s >>= 1) {
        if (t < s) { r1[t] += r1[t + s]; r2[t] += r2[t + s]; }
        __syncthreads();
    }
    if (t == 0) { g_p[i] = r1[0]; g_q[i] = r2[0]; }
}

// ---------------- sparse masked-softmax attention ------------------------------
// One row per block, 128 threads. Softmax weights below exp(-25) of the max
// contribute < 1.4e-11 each (total dropped mass < N*exp(-25) ~ 4e-8) and are
// skipped in BOTH numerator and denominator (consistent truncation).
// Deterministic: ballot prefix-compaction in ascending-j order, tree reductions.
__global__ void __launch_bounds__(128) attn_sparse(const int* __restrict__ A,
                                                   float* __restrict__ H) {
    __shared__ int   sj[N];        // selected j (ascending)
    __shared__ float sx[N];        // logit, then weight
    __shared__ float red[128];
    __shared__ int   scnt;
    __shared__ int   wbase[4];

    int i    = blockIdx.x;
    int t    = threadIdx.x;
    int lane = t & 31;
    int wid  = t >> 5;
    float p  = g_p[i];
    float q  = g_q[i];
    const int* Arow = A + (size_t)i * N;

    // ---- pass 1: masked row max --------------------------------------------
    float mx = 0.f;
    for (int j = t; j < N; j += 128)
        if (Arow[j]) mx = fmaxf(mx, fabsf(p + q * __ldg(&g_k2[j])));
    red[t] = mx;
    __syncthreads();
    for (int s = 64; s; s >>= 1) {
        if (t < s) red[t] = fmaxf(red[t], red[t + s]);
        __syncthreads();
    }
    float m = red[0];
    if (t == 0) scnt = 0;
    __syncthreads();
    float thr = m - XTHR;

    // ---- pass 2: deterministic compaction of j with x > m - 25 --------------
    for (int jb = 0; jb < NPAD; jb += 128) {
        int j = jb + t;
        bool pred = false;
        float x = 0.f;
        if (j < N && Arow[j]) {
            x = fabsf(p + q * __ldg(&g_k2[j]));
            pred = (x > thr);
        }
        unsigned bal = __ballot_sync(0xffffffffu, pred);
        int pos  = __popc(bal & ((1u << lane) - 1u));
        if (lane == 0) wbase[wid] = __popc(bal);
        __syncthreads();
        if (t == 0) {
            int b0 = scnt;
#pragma unroll
            for (int w = 0; w < 4; w++) { int tmp = wbase[w]; wbase[w] = b0; b0 += tmp; }
            scnt = b0;
        }
        __syncthreads();
        if (pred) { int idx = wbase[wid] + pos; sj[idx] = j; sx[idx] = x; }
        __syncthreads();
    }
    int cnt = scnt;

    // ---- weights + denominator (tree reduce, deterministic) -----------------
    float ls = 0.f;
    for (int e = t; e < cnt; e += 128) {
        float w = __expf(sx[e] - m);
        sx[e] = w;
        ls += w;
    }
    red[t] = ls;
    __syncthreads();
    for (int s = 64; s; s >>= 1) {
        if (t < s) red[t] += red[t + s];
        __syncthreads();
    }
    float l = red[0];
    float inv = (l > 0.f) ? 1.f / l : 0.f;

    // ---- numerator: thread t = output column t, gather selected K rows ------
    float a0 = 0.f, a1 = 0.f, a2 = 0.f, a3 = 0.f;
    int e = 0;
    for (; e + 4 <= cnt; e += 4) {
        a0 += sx[e + 0] * __ldg(&g_K[(size_t)sj[e + 0] * OC + t]);
        a1 += sx[e + 1] * __ldg(&g_K[(size_t)sj[e + 1] * OC + t]);
        a2 += sx[e + 2] * __ldg(&g_K[(size_t)sj[e + 2] * OC + t]);
        a3 += sx[e + 3] * __ldg(&g_K[(size_t)sj[e + 3] * OC + t]);
    }
    for (; e < cnt; e++)
        a0 += sx[e] * __ldg(&g_K[(size_t)sj[e] * OC + t]);
    float acc = (a0 + a1) + (a2 + a3);
    H[(size_t)i * OC + t] = acc * inv;
}

// ---------------- launch --------------------------------------------------------
extern "C" void kernel_launch(void* const* d_in, const int* in_sizes, int n_in,
                              void* d_out, int out_size) {
    (void)in_sizes; (void)n_in; (void)out_size;
    const float* X    = (const float*)d_in[0];
    const int*   A    = (const int*)d_in[1];
    const float* U    = (const float*)d_in[2];
    const float* W    = (const float*)d_in[3];
    const float* a1   = (const float*)d_in[4];
    const float* a2   = (const float*)d_in[5];
    const float* lmbd = (const float*)d_in[6];
    float* H = (float*)d_out;

    gemm_k     <<<dim3(2, (N + 31) / 32, GZ), 128>>>(X, W);
    fold_k1k2  <<<(N + 7) / 8, 256>>>(a1, a2);
    colpart    <<<dim3((N + 255) / 256, NCH), 256>>>(U);
    colreduce  <<<(N + 255) / 256, 256>>>(lmbd);
    pq_kernel  <<<N, 256>>>(U);
    attn_sparse<<<N, 128>>>(A, H);
}